// round 3
// baseline (speedup 1.0000x reference)
#include <cuda_runtime.h>
#include <cstdint>

#define NN 20000
#define EE 160000
#define E2 320000
#define HD 128

// ---------------- static scratch (no allocations allowed) ----------------
static __device__ float g_A[NN * HD];
static __device__ float g_B[NN * HD];
static __device__ float g_C[NN * HD];
static __device__ float g_H[NN * HD];
static __device__ float g_T[NN * HD];
static __device__ float g_R[(size_t)EE * HD];     // per-original-edge ea@W1_e + b1
static __device__ float g_h16[NN * 16];
static __device__ float g_norm[E2];
static __device__ float g_degf[NN];
static __device__ float g_dis[NN];
static __device__ int   g_deg[NN];
static __device__ int   g_cnt[NN];
static __device__ int   g_off[NN + 1];
static __device__ int   g_csr_src[E2];
static __device__ int   g_csr_rid[E2];

// ---------------- CSR build ----------------
__global__ void k_hist(const int* __restrict__ ei) {
    int e = blockIdx.x * blockDim.x + threadIdx.x;
    if (e >= EE) return;
    int s = ei[e], d = ei[EE + e];
    atomicAdd(&g_deg[d], 1);
    atomicAdd(&g_deg[s], 1);
}

__global__ void k_scan() {  // single block, 1024 threads
    __shared__ int part[1024];
    const int CH = (NN + 1023) / 1024;  // 20
    int t = threadIdx.x;
    int base = t * CH;
    int s = 0;
    for (int j = 0; j < CH; j++) {
        int idx = base + j;
        if (idx < NN) s += g_deg[idx];
    }
    part[t] = s;
    __syncthreads();
    for (int off = 1; off < 1024; off <<= 1) {
        int v = (t >= off) ? part[t - off] : 0;
        __syncthreads();
        part[t] += v;
        __syncthreads();
    }
    int run = (t > 0) ? part[t - 1] : 0;
    for (int j = 0; j < CH; j++) {
        int idx = base + j;
        if (idx < NN) {
            g_off[idx] = run;
            int d = g_deg[idx];
            run += d;
            g_degf[idx] = (float)d;
            g_dis[idx]  = (d > 0) ? rsqrtf((float)d) : 0.0f;
        }
    }
    if (t == 1023) g_off[NN] = run;
}

__global__ void k_fill(const int* __restrict__ ei) {
    int e = blockIdx.x * blockDim.x + threadIdx.x;
    if (e >= EE) return;
    int s0 = ei[e], d0 = ei[EE + e];
    int p = atomicAdd(&g_cnt[d0], 1);
    int slot = g_off[d0] + p;
    g_csr_src[slot] = s0;
    g_csr_rid[slot] = e;
    p = atomicAdd(&g_cnt[s0], 1);
    slot = g_off[s0] + p;
    g_csr_src[slot] = d0;
    g_csr_rid[slot] = e;
}

__global__ void k_norm() {
    int i = blockIdx.x * blockDim.x + threadIdx.x;
    if (i >= NN) return;
    float di = g_dis[i];
    int s1 = g_off[i + 1];
    for (int s = g_off[i]; s < s1; s++)
        g_norm[s] = di * g_dis[g_csr_src[s]];
}

// ---------------- generic fp32 GEMM: D = A[M,K] @ B[K,Nc] (+Cin)(+bias*rowscale)(relu) --------
__global__ __launch_bounds__(256)
void k_gemm(const float* __restrict__ A, const float* __restrict__ B,
            float* __restrict__ D, const float* __restrict__ Cin,
            const float* __restrict__ bias, const float* __restrict__ rowscale,
            int M, int K, int Nc, int relu) {
    const int BM = 128, BN = 128, BK = 16;
    __shared__ float As[BK][BM];
    __shared__ float Bs[BK][BN];
    int tid = threadIdx.x;
    int tx = tid & 15, ty = tid >> 4;
    int row0 = blockIdx.y * BM, col0 = blockIdx.x * BN;
    float acc[8][8];
#pragma unroll
    for (int i = 0; i < 8; i++)
#pragma unroll
        for (int j = 0; j < 8; j++) acc[i][j] = 0.0f;

    for (int k0 = 0; k0 < K; k0 += BK) {
        // A tile: 128x16 (transposed into As[k][m])
#pragma unroll
        for (int i = 0; i < 2; i++) {
            int v = tid + i * 256;      // 0..511 float4 slots
            int r = v >> 2;
            int kk = (v & 3) * 4;
            float4 a = make_float4(0.f, 0.f, 0.f, 0.f);
            int gr = row0 + r;
            if (gr < M && (k0 + kk + 3) < K)
                a = *(const float4*)(A + (size_t)gr * K + k0 + kk);
            else if (gr < M) {
                float tmp[4] = {0.f, 0.f, 0.f, 0.f};
                for (int j = 0; j < 4; j++)
                    if (k0 + kk + j < K) tmp[j] = A[(size_t)gr * K + k0 + kk + j];
                a = make_float4(tmp[0], tmp[1], tmp[2], tmp[3]);
            }
            As[kk + 0][r] = a.x; As[kk + 1][r] = a.y;
            As[kk + 2][r] = a.z; As[kk + 3][r] = a.w;
        }
        // B tile: 16x128
#pragma unroll
        for (int i = 0; i < 2; i++) {
            int v = tid + i * 256;
            int kr = v >> 5;
            int c = (v & 31) * 4;
            float4 b = make_float4(0.f, 0.f, 0.f, 0.f);
            int gk = k0 + kr, gc = col0 + c;
            if (gk < K && (gc + 3) < Nc)
                b = *(const float4*)(B + (size_t)gk * Nc + gc);
            Bs[kr][c + 0] = b.x; Bs[kr][c + 1] = b.y;
            Bs[kr][c + 2] = b.z; Bs[kr][c + 3] = b.w;
        }
        __syncthreads();
#pragma unroll
        for (int kk = 0; kk < BK; kk++) {
            float a[8], b[8];
            *(float4*)(a)     = *(const float4*)&As[kk][ty * 8];
            *(float4*)(a + 4) = *(const float4*)&As[kk][ty * 8 + 4];
            *(float4*)(b)     = *(const float4*)&Bs[kk][tx * 8];
            *(float4*)(b + 4) = *(const float4*)&Bs[kk][tx * 8 + 4];
#pragma unroll
            for (int i = 0; i < 8; i++)
#pragma unroll
                for (int j = 0; j < 8; j++) acc[i][j] += a[i] * b[j];
        }
        __syncthreads();
    }
    // epilogue
#pragma unroll
    for (int i = 0; i < 8; i++) {
        int m = row0 + ty * 8 + i;
        if (m >= M) continue;
        float rs = rowscale ? rowscale[m] : 1.0f;
#pragma unroll
        for (int j = 0; j < 8; j++) {
            int n = col0 + tx * 8 + j;
            if (n >= Nc) continue;
            float v = acc[i][j];
            if (Cin)  v += Cin[(size_t)m * Nc + n];
            if (bias) v += rs * bias[n];
            if (relu) v = fmaxf(v, 0.0f);
            D[(size_t)m * Nc + n] = v;
        }
    }
}

// ---------------- R = edge_attr @ W1_e + b1  (per original edge) ----------------
__global__ __launch_bounds__(256)
void k_R(const float* __restrict__ EA, const float* __restrict__ W,
         const float* __restrict__ b1) {
    __shared__ float sw[16 * 128];
    __shared__ float sb[128];
    for (int v = threadIdx.x; v < 2048; v += blockDim.x) sw[v] = W[v];
    for (int v = threadIdx.x; v < 128; v += blockDim.x) sb[v] = b1[v];
    __syncthreads();
    int lane = threadIdx.x & 31;
    int f = lane * 4;
    float w[16][4];
#pragma unroll
    for (int k = 0; k < 16; k++) {
        float4 t = *(const float4*)&sw[k * 128 + f];
        w[k][0] = t.x; w[k][1] = t.y; w[k][2] = t.z; w[k][3] = t.w;
    }
    float4 bb = *(const float4*)&sb[f];
    int warpsPerBlock = blockDim.x >> 5;
    int warp = blockIdx.x * warpsPerBlock + (threadIdx.x >> 5);
    int nwarps = gridDim.x * warpsPerBlock;
    for (int e = warp; e < EE; e += nwarps) {
        float val = (lane < 16) ? EA[(size_t)e * 16 + lane] : 0.0f;
        float4 acc = bb;
#pragma unroll
        for (int k = 0; k < 16; k++) {
            float a = __shfl_sync(0xffffffffu, val, k);
            acc.x += a * w[k][0]; acc.y += a * w[k][1];
            acc.z += a * w[k][2]; acc.w += a * w[k][3];
        }
        *(float4*)(g_R + (size_t)e * HD + f) = acc;
    }
}

// ---------------- EA edge pass: S[i] = sum_e relu(P[i]+Q[src]+R[rid]) -------------
__global__ __launch_bounds__(256)
void k_edge(const float* __restrict__ P, const float* __restrict__ Q,
            const float* __restrict__ Rm, float* __restrict__ S) {
    int warp = (blockIdx.x * blockDim.x + threadIdx.x) >> 5;
    if (warp >= NN) return;
    int lane = threadIdx.x & 31;
    int f = lane * 4;
    int i = warp;
    float4 p = *(const float4*)(P + (size_t)i * HD + f);
    float4 acc = make_float4(0.f, 0.f, 0.f, 0.f);
    int s1 = g_off[i + 1];
    for (int s = g_off[i]; s < s1; s++) {
        int src = g_csr_src[s];
        int rid = g_csr_rid[s];
        float4 q = *(const float4*)(Q + (size_t)src * HD + f);
        float4 r = *(const float4*)(Rm + (size_t)rid * HD + f);
        acc.x += fmaxf(p.x + q.x + r.x, 0.f);
        acc.y += fmaxf(p.y + q.y + r.y, 0.f);
        acc.z += fmaxf(p.z + q.z + r.z, 0.f);
        acc.w += fmaxf(p.w + q.w + r.w, 0.f);
    }
    *(float4*)(S + (size_t)i * HD + f) = acc;
}

// ---------------- TAG propagation: Hn[i] = sum_e norm[e]*Hc[src] ----------------
__global__ __launch_bounds__(256)
void k_prop(const float* __restrict__ Hc, float* __restrict__ Hn) {
    int warp = (blockIdx.x * blockDim.x + threadIdx.x) >> 5;
    if (warp >= NN) return;
    int lane = threadIdx.x & 31;
    int f = lane * 4;
    int i = warp;
    float4 acc = make_float4(0.f, 0.f, 0.f, 0.f);
    int s1 = g_off[i + 1];
    for (int s = g_off[i]; s < s1; s++) {
        int src = g_csr_src[s];
        float nm = g_norm[s];
        float4 h = *(const float4*)(Hc + (size_t)src * HD + f);
        acc.x += nm * h.x; acc.y += nm * h.y;
        acc.z += nm * h.z; acc.w += nm * h.w;
    }
    *(float4*)(Hn + (size_t)i * HD + f) = acc;
}

// ---------------- host ----------------
static void gemm(const float* A, const float* B, float* D, const float* Cin,
                 const float* bias, const float* rowscale,
                 int M, int K, int Nc, int relu) {
    dim3 grid((Nc + 127) / 128, (M + 127) / 128);
    k_gemm<<<grid, 256>>>(A, B, D, Cin, bias, rowscale, M, K, Nc, relu);
}

extern "C" void kernel_launch(void* const* d_in, const int* in_sizes, int n_in,
                              void* d_out, int out_size) {
    const float* x         = (const float*)d_in[0];
    const float* mask      = (const float*)d_in[1];
    const float* edge_attr = (const float*)d_in[2];
    const int* edge_index;
    int base;
    if (in_sizes[3] == 2 * EE) {           // setup_inputs dict order
        edge_index = (const int*)d_in[3];
        base = 4;
    } else {                               // reference-signature order (edge_index last)
        edge_index = (const int*)d_in[n_in - 1];
        base = 3;
    }
    const float* m_w1  = (const float*)d_in[base + 0];
    const float* m_b1  = (const float*)d_in[base + 1];
    const float* m_w2  = (const float*)d_in[base + 2];
    const float* m_b2  = (const float*)d_in[base + 3];
    const float* ea0_w1 = (const float*)d_in[base + 4];
    const float* ea0_b1 = (const float*)d_in[base + 5];
    const float* ea0_w2 = (const float*)d_in[base + 6];
    const float* ea0_b2 = (const float*)d_in[base + 7];
    const float* tag0_w = (const float*)d_in[base + 8];
    const float* tag0_b = (const float*)d_in[base + 9];
    const float* ea1_w1 = (const float*)d_in[base + 10];
    const float* ea1_b1 = (const float*)d_in[base + 11];
    const float* ea1_w2 = (const float*)d_in[base + 12];
    const float* ea1_b2 = (const float*)d_in[base + 13];
    const float* tag1_w = (const float*)d_in[base + 14];
    const float* tag1_b = (const float*)d_in[base + 15];
    const float* ea2_w1 = (const float*)d_in[base + 16];
    const float* ea2_b1 = (const float*)d_in[base + 17];
    const float* ea2_w2 = (const float*)d_in[base + 18];
    const float* ea2_b2 = (const float*)d_in[base + 19];

    float *pA, *pB, *pC, *pH, *pT, *pR, *ph16, *pdegf;
    int *pdeg, *pcnt;
    cudaGetSymbolAddress((void**)&pA, g_A);
    cudaGetSymbolAddress((void**)&pB, g_B);
    cudaGetSymbolAddress((void**)&pC, g_C);
    cudaGetSymbolAddress((void**)&pH, g_H);
    cudaGetSymbolAddress((void**)&pT, g_T);
    cudaGetSymbolAddress((void**)&pR, g_R);
    cudaGetSymbolAddress((void**)&ph16, g_h16);
    cudaGetSymbolAddress((void**)&pdegf, g_degf);
    cudaGetSymbolAddress((void**)&pdeg, g_deg);
    cudaGetSymbolAddress((void**)&pcnt, g_cnt);

    // ---- CSR + norm preprocessing ----
    cudaMemsetAsync(pdeg, 0, NN * sizeof(int));
    k_hist<<<(EE + 255) / 256, 256>>>(edge_index);
    k_scan<<<1, 1024>>>();
    cudaMemsetAsync(pcnt, 0, NN * sizeof(int));
    k_fill<<<(EE + 255) / 256, 256>>>(edge_index);
    k_norm<<<(NN + 255) / 256, 256>>>();

    const int EB = 2500;  // node-warp blocks (20000 nodes / 8 warps)

    // ---- mask MLP + residual: h16 = relu(mask@w1+b1)@w2 + b2 + x ----
    gemm(mask, m_w1, pT, nullptr, m_b1, nullptr, NN, 16, 128, 1);
    gemm(pT, m_w2, ph16, x, m_b2, nullptr, NN, 128, 16, 0);

    // ---- EA0 (in=16) ----
    gemm(ph16, ea0_w1,             pA, nullptr, nullptr, nullptr, NN, 16, 128, 0);
    gemm(ph16, ea0_w1 + 16 * 128,  pB, nullptr, nullptr, nullptr, NN, 16, 128, 0);
    k_R<<<512, 256>>>(edge_attr, ea0_w1 + 32 * 128, ea0_b1);
    k_edge<<<EB, 256>>>(pA, pB, pR, pC);
    gemm(pC, ea0_w2, pH, nullptr, ea0_b2, pdegf, NN, 128, 128, 1);

    // ---- TAG0 ----
    gemm(pH, tag0_w, pA, nullptr, nullptr, nullptr, NN, 128, 128, 0);
    k_prop<<<EB, 256>>>(pH, pB);
    gemm(pB, tag0_w + 1 * 16384, pA, pA, nullptr, nullptr, NN, 128, 128, 0);
    k_prop<<<EB, 256>>>(pB, pC);
    gemm(pC, tag0_w + 2 * 16384, pA, pA, nullptr, nullptr, NN, 128, 128, 0);
    k_prop<<<EB, 256>>>(pC, pB);
    gemm(pB, tag0_w + 3 * 16384, pH, pA, tag0_b, nullptr, NN, 128, 128, 1);

    // ---- EA1 (in=128) ----
    gemm(pH, ea1_w1,              pA, nullptr, nullptr, nullptr, NN, 128, 128, 0);
    gemm(pH, ea1_w1 + 128 * 128,  pB, nullptr, nullptr, nullptr, NN, 128, 128, 0);
    k_R<<<512, 256>>>(edge_attr, ea1_w1 + 256 * 128, ea1_b1);
    k_edge<<<EB, 256>>>(pA, pB, pR, pC);
    gemm(pC, ea1_w2, pH, nullptr, ea1_b2, pdegf, NN, 128, 128, 1);

    // ---- TAG1 ----
    gemm(pH, tag1_w, pA, nullptr, nullptr, nullptr, NN, 128, 128, 0);
    k_prop<<<EB, 256>>>(pH, pB);
    gemm(pB, tag1_w + 1 * 16384, pA, pA, nullptr, nullptr, NN, 128, 128, 0);
    k_prop<<<EB, 256>>>(pB, pC);
    gemm(pC, tag1_w + 2 * 16384, pA, pA, nullptr, nullptr, NN, 128, 128, 0);
    k_prop<<<EB, 256>>>(pC, pB);
    gemm(pB, tag1_w + 3 * 16384, pH, pA, tag1_b, nullptr, NN, 128, 128, 1);

    // ---- EA2 (final, no relu, out = [N,16]) ----
    gemm(pH, ea2_w1,              pA, nullptr, nullptr, nullptr, NN, 128, 128, 0);
    gemm(pH, ea2_w1 + 128 * 128,  pB, nullptr, nullptr, nullptr, NN, 128, 128, 0);
    k_R<<<512, 256>>>(edge_attr, ea2_w1 + 256 * 128, ea2_b1);
    k_edge<<<EB, 256>>>(pA, pB, pR, pC);
    gemm(pC, ea2_w2, (float*)d_out, nullptr, ea2_b2, pdegf, NN, 128, 16, 0);
}

// round 4
// speedup vs baseline: 1.2237x; 1.2237x over previous
#include <cuda_runtime.h>
#include <mma.h>
#include <cstdint>

#define NN 20000
#define EE 160000
#define E2 320000
#define HD 128

// ---------------- static scratch (no allocations allowed) ----------------
static __device__ float g_A[NN * HD];
static __device__ float g_B[NN * HD];
static __device__ float g_C[NN * HD];
static __device__ float g_H[NN * HD];
static __device__ float g_T[NN * HD];
static __device__ float g_X[(size_t)NN * 512];   // [h | Lh | L^2h | L^3h]
static __device__ float g_h16[NN * 16];
static __device__ float g_norm[E2];
static __device__ float g_degf[NN];
static __device__ float g_dis[NN];
static __device__ int   g_deg[NN];
static __device__ int   g_cnt[NN];
static __device__ int   g_off[NN + 1];
static __device__ int   g_csr_src[E2];
static __device__ int   g_csr_rid[E2];

// ---------------- CSR build ----------------
__global__ void k_hist(const int* __restrict__ ei) {
    int e = blockIdx.x * blockDim.x + threadIdx.x;
    if (e >= EE) return;
    int s = ei[e], d = ei[EE + e];
    atomicAdd(&g_deg[d], 1);
    atomicAdd(&g_deg[s], 1);
}

__global__ void k_scan() {  // single block, 1024 threads
    __shared__ int part[1024];
    const int CH = (NN + 1023) / 1024;  // 20
    int t = threadIdx.x;
    int base = t * CH;
    int s = 0;
    for (int j = 0; j < CH; j++) {
        int idx = base + j;
        if (idx < NN) s += g_deg[idx];
    }
    part[t] = s;
    __syncthreads();
    for (int off = 1; off < 1024; off <<= 1) {
        int v = (t >= off) ? part[t - off] : 0;
        __syncthreads();
        part[t] += v;
        __syncthreads();
    }
    int run = (t > 0) ? part[t - 1] : 0;
    for (int j = 0; j < CH; j++) {
        int idx = base + j;
        if (idx < NN) {
            g_off[idx] = run;
            int d = g_deg[idx];
            run += d;
            g_degf[idx] = (float)d;
            g_dis[idx]  = (d > 0) ? rsqrtf((float)d) : 0.0f;
        }
    }
    if (t == 1023) g_off[NN] = run;
}

__global__ void k_fill(const int* __restrict__ ei) {
    int e = blockIdx.x * blockDim.x + threadIdx.x;
    if (e >= EE) return;
    int s0 = ei[e], d0 = ei[EE + e];
    int p = atomicAdd(&g_cnt[d0], 1);
    int slot = g_off[d0] + p;
    g_csr_src[slot] = s0;
    g_csr_rid[slot] = e;
    p = atomicAdd(&g_cnt[s0], 1);
    slot = g_off[s0] + p;
    g_csr_src[slot] = d0;
    g_csr_rid[slot] = e;
}

__global__ void k_norm() {
    int i = blockIdx.x * blockDim.x + threadIdx.x;
    if (i >= NN) return;
    float di = g_dis[i];
    int s1 = g_off[i + 1];
    for (int s = g_off[i]; s < s1; s++)
        g_norm[s] = di * g_dis[g_csr_src[s]];
}

// ---------------- tf32 tensor-core GEMM ----------------
// D[M,N] = A[M,K] @ B[K,N] (+Cin)(+rowscale*bias)(relu). B row-major ld=N.
// Block tile 128x128, 8 warps (4m x 2n), warp tile 32x64, BK=16 double-buffered.
__global__ __launch_bounds__(256)
void k_gemm_tc(const float* __restrict__ A, int lda,
               const float* __restrict__ B,
               float* __restrict__ D, int ldd,
               const float* __restrict__ Cin, int ldc,
               const float* __restrict__ bias, const float* __restrict__ rowscale,
               int M, int K, int N, int relu) {
    using namespace nvcuda;
    __shared__ float As[2][128 * 20];   // 128 rows x 16 cols, padded ld=20
    __shared__ float Bs[2][16 * 136];   // 16 rows x 128 cols, padded ld=136
    int tid = threadIdx.x;
    int wid = tid >> 5, lane = tid & 31;
    int wm = wid >> 1, wn = wid & 1;
    int row0 = blockIdx.y * 128, col0 = blockIdx.x * 128;

    wmma::fragment<wmma::accumulator, 16, 16, 8, float> acc[2][4];
#pragma unroll
    for (int mi = 0; mi < 2; mi++)
#pragma unroll
        for (int ni = 0; ni < 4; ni++) wmma::fill_fragment(acc[mi][ni], 0.0f);

    int KT = K >> 4;

    auto loadA = [&](int kt, int buf) {
        int k0 = kt << 4;
#pragma unroll
        for (int i = 0; i < 2; i++) {
            int v = tid + (i << 8);
            int r = v >> 2, c = (v & 3) << 2;
            int gr = row0 + r;
            float4 a = make_float4(0.f, 0.f, 0.f, 0.f);
            if (gr < M) a = *(const float4*)(A + (size_t)gr * lda + k0 + c);
            *(float4*)&As[buf][r * 20 + c] = a;
        }
    };
    auto loadB = [&](int kt, int buf) {
        int k0 = kt << 4;
#pragma unroll
        for (int i = 0; i < 2; i++) {
            int v = tid + (i << 8);
            int r = v >> 5, c = (v & 31) << 2;
            int gc = col0 + c;
            float4 b = make_float4(0.f, 0.f, 0.f, 0.f);
            if (gc < N) b = *(const float4*)(B + (size_t)(k0 + r) * N + gc);
            *(float4*)&Bs[buf][r * 136 + c] = b;
        }
    };

    loadA(0, 0); loadB(0, 0);
    __syncthreads();
    for (int kt = 0; kt < KT; kt++) {
        int buf = kt & 1;
        if (kt + 1 < KT) { loadA(kt + 1, buf ^ 1); loadB(kt + 1, buf ^ 1); }
#pragma unroll
        for (int ks = 0; ks < 2; ks++) {
            wmma::fragment<wmma::matrix_a, 16, 16, 8, wmma::precision::tf32, wmma::row_major> af[2];
            wmma::fragment<wmma::matrix_b, 16, 16, 8, wmma::precision::tf32, wmma::row_major> bf[4];
#pragma unroll
            for (int mi = 0; mi < 2; mi++) {
                wmma::load_matrix_sync(af[mi], &As[buf][(wm * 32 + mi * 16) * 20 + ks * 8], 20);
#pragma unroll
                for (int t = 0; t < af[mi].num_elements; t++)
                    af[mi].x[t] = wmma::__float_to_tf32(af[mi].x[t]);
            }
#pragma unroll
            for (int ni = 0; ni < 4; ni++) {
                wmma::load_matrix_sync(bf[ni], &Bs[buf][(ks * 8) * 136 + wn * 64 + ni * 16], 136);
#pragma unroll
                for (int t = 0; t < bf[ni].num_elements; t++)
                    bf[ni].x[t] = wmma::__float_to_tf32(bf[ni].x[t]);
            }
#pragma unroll
            for (int mi = 0; mi < 2; mi++)
#pragma unroll
                for (int ni = 0; ni < 4; ni++)
                    wmma::mma_sync(acc[mi][ni], af[mi], bf[ni], acc[mi][ni]);
        }
        __syncthreads();
    }

    // epilogue: per-warp frag staging in As[0] (ld=20, 16x20 floats per warp)
    float* epi = &As[0][0] + wid * 320;
#pragma unroll
    for (int mi = 0; mi < 2; mi++) {
#pragma unroll
        for (int ni = 0; ni < 4; ni++) {
            int nb = col0 + wn * 64 + ni * 16;
            if (nb >= N) continue;  // warp-uniform
            wmma::store_matrix_sync(epi, acc[mi][ni], 20, wmma::mem_row_major);
            __syncwarp();
            int r = lane >> 1, cb = (lane & 1) * 8;
            int m = row0 + wm * 32 + mi * 16 + r;
            if (m < M) {
                float rs = rowscale ? rowscale[m] : 1.0f;
                float4 v0 = *(float4*)&epi[r * 20 + cb];
                float4 v1 = *(float4*)&epi[r * 20 + cb + 4];
                if (Cin) {
                    float4 c0 = *(const float4*)(Cin + (size_t)m * ldc + nb + cb);
                    float4 c1 = *(const float4*)(Cin + (size_t)m * ldc + nb + cb + 4);
                    v0.x += c0.x; v0.y += c0.y; v0.z += c0.z; v0.w += c0.w;
                    v1.x += c1.x; v1.y += c1.y; v1.z += c1.z; v1.w += c1.w;
                }
                if (bias) {
                    float4 b0 = *(const float4*)(bias + nb + cb);
                    float4 b1 = *(const float4*)(bias + nb + cb + 4);
                    v0.x += rs * b0.x; v0.y += rs * b0.y; v0.z += rs * b0.z; v0.w += rs * b0.w;
                    v1.x += rs * b1.x; v1.y += rs * b1.y; v1.z += rs * b1.z; v1.w += rs * b1.w;
                }
                if (relu) {
                    v0.x = fmaxf(v0.x, 0.f); v0.y = fmaxf(v0.y, 0.f);
                    v0.z = fmaxf(v0.z, 0.f); v0.w = fmaxf(v0.w, 0.f);
                    v1.x = fmaxf(v1.x, 0.f); v1.y = fmaxf(v1.y, 0.f);
                    v1.z = fmaxf(v1.z, 0.f); v1.w = fmaxf(v1.w, 0.f);
                }
                *(float4*)(D + (size_t)m * ldd + nb + cb)     = v0;
                *(float4*)(D + (size_t)m * ldd + nb + cb + 4) = v1;
            }
            __syncwarp();
        }
    }
}

// ---------------- fused EA edge pass ----------------
// S[i] = sum_neighbors relu( P[i] + Q[src] + (ea[rid] @ W1e + b1) )
__global__ __launch_bounds__(256)
void k_edge_f(const float* __restrict__ P, const float* __restrict__ Q,
              const float* __restrict__ EA, const float* __restrict__ W1e,
              const float* __restrict__ b1, float* __restrict__ S) {
    __shared__ float sw[16 * 128];
    __shared__ float sb[128];
    for (int v = threadIdx.x; v < 2048; v += blockDim.x) sw[v] = W1e[v];
    for (int v = threadIdx.x; v < 128; v += blockDim.x) sb[v] = b1[v];
    __syncthreads();
    int lane = threadIdx.x & 31;
    int f = lane * 4;
    float w[16][4];
#pragma unroll
    for (int k = 0; k < 16; k++) {
        float4 t = *(const float4*)&sw[k * 128 + f];
        w[k][0] = t.x; w[k][1] = t.y; w[k][2] = t.z; w[k][3] = t.w;
    }
    float4 bb = *(const float4*)&sb[f];

    int i = (blockIdx.x * blockDim.x + threadIdx.x) >> 5;
    if (i >= NN) return;
    float4 p = *(const float4*)(P + (size_t)i * HD + f);
    float4 acc = make_float4(0.f, 0.f, 0.f, 0.f);
    int s1 = g_off[i + 1];
    for (int s = g_off[i]; s < s1; s++) {
        int src = g_csr_src[s];
        int rid = g_csr_rid[s];
        float val = (lane < 16) ? EA[(size_t)rid * 16 + lane] : 0.0f;
        float4 q = *(const float4*)(Q + (size_t)src * HD + f);
        float4 r = bb;
#pragma unroll
        for (int k = 0; k < 16; k++) {
            float a = __shfl_sync(0xffffffffu, val, k);
            r.x += a * w[k][0]; r.y += a * w[k][1];
            r.z += a * w[k][2]; r.w += a * w[k][3];
        }
        acc.x += fmaxf(p.x + q.x + r.x, 0.f);
        acc.y += fmaxf(p.y + q.y + r.y, 0.f);
        acc.z += fmaxf(p.z + q.z + r.z, 0.f);
        acc.w += fmaxf(p.w + q.w + r.w, 0.f);
    }
    *(float4*)(S + (size_t)i * HD + f) = acc;
}

// ---------------- TAG propagation within g_X (ld=512) ----------------
// Hn[i, off+128..] = sum_neighbors norm[e] * X[src, off..off+127]
__global__ __launch_bounds__(256)
void k_prop(const float* __restrict__ Xc, float* __restrict__ Xn) {
    int i = (blockIdx.x * blockDim.x + threadIdx.x) >> 5;
    if (i >= NN) return;
    int lane = threadIdx.x & 31;
    int f = lane * 4;
    float4 acc = make_float4(0.f, 0.f, 0.f, 0.f);
    int s1 = g_off[i + 1];
    for (int s = g_off[i]; s < s1; s++) {
        int src = g_csr_src[s];
        float nm = g_norm[s];
        float4 h = *(const float4*)(Xc + (size_t)src * 512 + f);
        acc.x += nm * h.x; acc.y += nm * h.y;
        acc.z += nm * h.z; acc.w += nm * h.w;
    }
    *(float4*)(Xn + (size_t)i * 512 + f) = acc;
}

// ---------------- host ----------------
static void gemm(const float* A, int lda, const float* B, float* D, int ldd,
                 const float* Cin, int ldc, const float* bias, const float* rowscale,
                 int M, int K, int N, int relu) {
    dim3 grid((N + 127) / 128, (M + 127) / 128);
    k_gemm_tc<<<grid, 256>>>(A, lda, B, D, ldd, Cin, ldc, bias, rowscale, M, K, N, relu);
}

extern "C" void kernel_launch(void* const* d_in, const int* in_sizes, int n_in,
                              void* d_out, int out_size) {
    const float* x         = (const float*)d_in[0];
    const float* mask      = (const float*)d_in[1];
    const float* edge_attr = (const float*)d_in[2];
    const int* edge_index;
    int base;
    if (in_sizes[3] == 2 * EE) {           // setup_inputs dict order
        edge_index = (const int*)d_in[3];
        base = 4;
    } else {                               // reference-signature order (edge_index last)
        edge_index = (const int*)d_in[n_in - 1];
        base = 3;
    }
    const float* m_w1   = (const float*)d_in[base + 0];
    const float* m_b1   = (const float*)d_in[base + 1];
    const float* m_w2   = (const float*)d_in[base + 2];
    const float* m_b2   = (const float*)d_in[base + 3];
    const float* ea0_w1 = (const float*)d_in[base + 4];
    const float* ea0_b1 = (const float*)d_in[base + 5];
    const float* ea0_w2 = (const float*)d_in[base + 6];
    const float* ea0_b2 = (const float*)d_in[base + 7];
    const float* tag0_w = (const float*)d_in[base + 8];
    const float* tag0_b = (const float*)d_in[base + 9];
    const float* ea1_w1 = (const float*)d_in[base + 10];
    const float* ea1_b1 = (const float*)d_in[base + 11];
    const float* ea1_w2 = (const float*)d_in[base + 12];
    const float* ea1_b2 = (const float*)d_in[base + 13];
    const float* tag1_w = (const float*)d_in[base + 14];
    const float* tag1_b = (const float*)d_in[base + 15];
    const float* ea2_w1 = (const float*)d_in[base + 16];
    const float* ea2_b1 = (const float*)d_in[base + 17];
    const float* ea2_w2 = (const float*)d_in[base + 18];
    const float* ea2_b2 = (const float*)d_in[base + 19];

    float *pA, *pB, *pC, *pH, *pT, *pX, *ph16, *pdegf;
    int *pdeg, *pcnt;
    cudaGetSymbolAddress((void**)&pA, g_A);
    cudaGetSymbolAddress((void**)&pB, g_B);
    cudaGetSymbolAddress((void**)&pC, g_C);
    cudaGetSymbolAddress((void**)&pH, g_H);
    cudaGetSymbolAddress((void**)&pT, g_T);
    cudaGetSymbolAddress((void**)&pX, g_X);
    cudaGetSymbolAddress((void**)&ph16, g_h16);
    cudaGetSymbolAddress((void**)&pdegf, g_degf);
    cudaGetSymbolAddress((void**)&pdeg, g_deg);
    cudaGetSymbolAddress((void**)&pcnt, g_cnt);

    // ---- CSR + norm preprocessing ----
    cudaMemsetAsync(pdeg, 0, NN * sizeof(int));
    k_hist<<<(EE + 255) / 256, 256>>>(edge_index);
    k_scan<<<1, 1024>>>();
    cudaMemsetAsync(pcnt, 0, NN * sizeof(int));
    k_fill<<<(EE + 255) / 256, 256>>>(edge_index);
    k_norm<<<(NN + 255) / 256, 256>>>();

    const int EB = 2500;  // 20000 node-warps / 8 warps per block

    // ---- mask MLP + residual: h16 = relu(mask@w1+b1)@w2 + b2 + x ----
    gemm(mask, 16, m_w1, pT, 128, nullptr, 0, m_b1, nullptr, NN, 16, 128, 1);
    gemm(pT, 128, m_w2, ph16, 16, x, 16, m_b2, nullptr, NN, 128, 16, 0);

    // ---- EA0 (in=16): h -> X[:,0:128] ----
    gemm(ph16, 16, ea0_w1,            pA, 128, nullptr, 0, nullptr, nullptr, NN, 16, 128, 0);
    gemm(ph16, 16, ea0_w1 + 16 * 128, pB, 128, nullptr, 0, nullptr, nullptr, NN, 16, 128, 0);
    k_edge_f<<<EB, 256>>>(pA, pB, edge_attr, ea0_w1 + 32 * 128, ea0_b1, pC);
    gemm(pC, 128, ea0_w2, pX, 512, nullptr, 0, ea0_b2, pdegf, NN, 128, 128, 1);

    // ---- TAG0: props fill X slices, one K=512 GEMM ----
    k_prop<<<EB, 256>>>(pX,       pX + 128);
    k_prop<<<EB, 256>>>(pX + 128, pX + 256);
    k_prop<<<EB, 256>>>(pX + 256, pX + 384);
    gemm(pX, 512, tag0_w, pH, 128, nullptr, 0, tag0_b, nullptr, NN, 512, 128, 1);

    // ---- EA1 (in=128) -> X[:,0:128] ----
    gemm(pH, 128, ea1_w1,             pA, 128, nullptr, 0, nullptr, nullptr, NN, 128, 128, 0);
    gemm(pH, 128, ea1_w1 + 128 * 128, pB, 128, nullptr, 0, nullptr, nullptr, NN, 128, 128, 0);
    k_edge_f<<<EB, 256>>>(pA, pB, edge_attr, ea1_w1 + 256 * 128, ea1_b1, pC);
    gemm(pC, 128, ea1_w2, pX, 512, nullptr, 0, ea1_b2, pdegf, NN, 128, 128, 1);

    // ---- TAG1 ----
    k_prop<<<EB, 256>>>(pX,       pX + 128);
    k_prop<<<EB, 256>>>(pX + 128, pX + 256);
    k_prop<<<EB, 256>>>(pX + 256, pX + 384);
    gemm(pX, 512, tag1_w, pH, 128, nullptr, 0, tag1_b, nullptr, NN, 512, 128, 1);

    // ---- EA2 (final, no relu, out = [N,16]) ----
    gemm(pH, 128, ea2_w1,             pA, 128, nullptr, 0, nullptr, nullptr, NN, 128, 128, 0);
    gemm(pH, 128, ea2_w1 + 128 * 128, pB, 128, nullptr, 0, nullptr, nullptr, NN, 128, 128, 0);
    k_edge_f<<<EB, 256>>>(pA, pB, edge_attr, ea2_w1 + 256 * 128, ea2_b1, pC);
    gemm(pC, 128, ea2_w2, (float*)d_out, 16, nullptr, 0, ea2_b2, pdegf, NN, 128, 16, 0);
}